// round 15
// baseline (speedup 1.0000x reference)
#include <cuda_runtime.h>
#include <cstdint>
#include <mma.h>
using namespace nvcuda;

// Problem constants
#define kN 50000
#define kNpad 50176   // padded per-relation row stride
#define kR 3
#define kE 300000
#define kH 4
#define kD 32
#define kF 128
#define kOUT 64

// ---------------- scratch (device globals; no allocations allowed) ----------
__device__ __align__(16) float g_feat[(size_t)kR * kNpad * kF];  // projected features
__device__ __align__(16) float g_el[(size_t)kR * kN * kH];
__device__ __align__(16) float g_er[(size_t)kR * kN * kH];
__device__ __align__(16) float g_h[(size_t)kN * kF];             // layer outputs (tf32-rounded)
__device__ __align__(16) float g_xtf[(size_t)kN * kF];           // tf32-rounded input x
__device__ __align__(16) float g_wtf[2 * kR * kF * kF];          // tf32-rounded W1|W2
// CSR (built once per launch; edges shared by both layers)
__device__ int g_hist[kR * kN];
__device__ int g_rowptr[kR * kN];
__device__ int g_cursor[kR * kN];
__device__ int g_edge[(size_t)kR * kE];  // src node ids, grouped by dst

// ---------------- cp.async helpers ------------------------------------------
__device__ __forceinline__ void cp_async16(uint32_t dst, const void* src, int src_bytes) {
    asm volatile("cp.async.cg.shared.global [%0], [%1], 16, %2;"
                 :: "r"(dst), "l"(src), "r"(src_bytes));
}
__device__ __forceinline__ void cp_commit() {
    asm volatile("cp.async.commit_group;");
}
template <int N>
__device__ __forceinline__ void cp_wait() {
    asm volatile("cp.async.wait_group %0;" :: "n"(N));
}

// ---------------- pre-conversion kernels (round to tf32 once) ---------------
__global__ void cvt_w_kernel(const float* __restrict__ W1, const float* __restrict__ W2) {
    int i = blockIdx.x * blockDim.x + threadIdx.x;
    const int nw = kR * kF * kF;
    if (i < nw)          g_wtf[i] = wmma::__float_to_tf32(W1[i]);
    else if (i < 2 * nw) g_wtf[i] = wmma::__float_to_tf32(W2[i - nw]);
}
__global__ void cvt_x_kernel(const float* __restrict__ x) {
    int i = blockIdx.x * blockDim.x + threadIdx.x;
    if (i >= kN * kF / 4) return;
    float4 v = ((const float4*)x)[i];
    v.x = wmma::__float_to_tf32(v.x); v.y = wmma::__float_to_tf32(v.y);
    v.z = wmma::__float_to_tf32(v.z); v.w = wmma::__float_to_tf32(v.w);
    ((float4*)g_xtf)[i] = v;
}

// ---------------- zero hist --------------------------------------------------
__global__ void zero_hist_kernel() {
    int idx = blockIdx.x * blockDim.x + threadIdx.x;
    if (idx < kR * kN) g_hist[idx] = 0;
}

// ---------------- CSR build --------------------------------------------------
__global__ void hist_kernel(const int* __restrict__ edges) {
    int idx = blockIdx.x * blockDim.x + threadIdx.x;
    if (idx >= kR * kE) return;
    int r = idx / kE, e = idx % kE;
    int dst = edges[(size_t)r * 2 * kE + kE + e];
    atomicAdd(&g_hist[r * kN + dst], 1);
}

__global__ __launch_bounds__(1024) void scan_kernel() {
    __shared__ int sums[1024];
    int r = blockIdx.x;
    int t = threadIdx.x;
    const int CH = (kN + 1023) / 1024;  // 49
    int begin = t * CH;
    int end = min(begin + CH, kN);
    int s = 0;
    for (int i = begin; i < end; i++) s += g_hist[r * kN + i];
    sums[t] = s;
    __syncthreads();
    for (int off = 1; off < 1024; off <<= 1) {
        int v = (t >= off) ? sums[t - off] : 0;
        __syncthreads();
        sums[t] += v;
        __syncthreads();
    }
    int running = sums[t] - s;  // exclusive
    for (int i = begin; i < end; i++) {
        g_rowptr[r * kN + i] = running;
        g_cursor[r * kN + i] = running;
        running += g_hist[r * kN + i];
    }
}

__global__ void scatter_kernel(const int* __restrict__ edges) {
    int idx = blockIdx.x * blockDim.x + threadIdx.x;
    if (idx >= kR * kE) return;
    int r = idx / kE, e = idx % kE;
    const int* eb = edges + (size_t)r * 2 * kE;
    int src = eb[e];
    int dst = eb[kE + e];
    int pos = atomicAdd(&g_cursor[r * kN + dst], 1);
    g_edge[(size_t)r * kE + pos] = src;
}

// ---------------- GEMM (tf32 WMMA, BM=128, cp.async double-buffer) ----------
// Inputs pre-rounded to tf32 -> no CVTs, no register prefetch. 2 CTAs/SM.
#define AS_LD 36
#define BS_LD 132
__global__ __launch_bounds__(256, 2) void gemm_feat_tc(
    const float* __restrict__ A, const float* __restrict__ W,
    const float* __restrict__ al, const float* __restrict__ ar) {
    extern __shared__ float smem[];
    float* As = smem;                      // [2][128][AS_LD]
    float* Bs = smem + 2 * 128 * AS_LD;    // [2][32][BS_LD]

    int r = blockIdx.z;
    int m0 = blockIdx.x * 128;
    const float* B = W + (size_t)r * kF * kF;
    float* C = g_feat + (size_t)r * kNpad * kF;

    int t = threadIdx.x;
    int w = t >> 5;
    int wm = w & 3;        // 32-row slab
    int wn = w >> 2;       // 64-col slab

    uint32_t as_base = (uint32_t)__cvta_generic_to_shared(As);
    uint32_t bs_base = (uint32_t)__cvta_generic_to_shared(Bs);

    // ---- stage chunk 0 ----
#pragma unroll
    for (int g = 0; g < 4; g++) {                  // A: 128x32 = 1024 float4
        int lin = g * 256 + t;
        int rr = lin >> 3;
        int cc = (lin & 7) * 4;
        int gr = m0 + rr;
        int ok = (gr < kN) ? 16 : 0;
        const float* src = A + (size_t)min(gr, kN - 1) * kF + cc;
        cp_async16(as_base + (rr * AS_LD + cc) * 4, src, ok);
    }
#pragma unroll
    for (int g = 0; g < 4; g++) {                  // B: 32x128 = 1024 float4
        int lin = g * 256 + t;
        int row = lin >> 5;
        int col = (lin & 31) * 4;
        cp_async16(bs_base + (row * BS_LD + col) * 4, B + (size_t)row * kF + col, 16);
    }
    cp_commit();

    wmma::fragment<wmma::accumulator, 16, 16, 8, float> acc[2][4];
#pragma unroll
    for (int i = 0; i < 2; i++)
#pragma unroll
        for (int j = 0; j < 4; j++) wmma::fill_fragment(acc[i][j], 0.f);

#pragma unroll
    for (int c = 0; c < 4; c++) {
        if (c < 3) {
            int buf = (c + 1) & 1;
#pragma unroll
            for (int g = 0; g < 4; g++) {
                int lin = g * 256 + t;
                int rr = lin >> 3;
                int cc = (lin & 7) * 4;
                int gr = m0 + rr;
                int ok = (gr < kN) ? 16 : 0;
                const float* src = A + (size_t)min(gr, kN - 1) * kF + (c + 1) * 32 + cc;
                cp_async16(as_base + (buf * 128 * AS_LD + rr * AS_LD + cc) * 4, src, ok);
            }
#pragma unroll
            for (int g = 0; g < 4; g++) {
                int lin = g * 256 + t;
                int row = lin >> 5;
                int col = (lin & 31) * 4;
                cp_async16(bs_base + (buf * 32 * BS_LD + row * BS_LD + col) * 4,
                           B + (size_t)((c + 1) * 32 + row) * kF + col, 16);
            }
            cp_commit();
            cp_wait<1>();
        } else {
            cp_wait<0>();
        }
        __syncthreads();

        const float* Ab = As + (c & 1) * 128 * AS_LD;
        const float* Bb = Bs + (c & 1) * 32 * BS_LD;
#pragma unroll
        for (int kk = 0; kk < 4; kk++) {
            wmma::fragment<wmma::matrix_a, 16, 16, 8, wmma::precision::tf32, wmma::row_major> fa[2];
            wmma::fragment<wmma::matrix_b, 16, 16, 8, wmma::precision::tf32, wmma::row_major> fb[4];
#pragma unroll
            for (int i = 0; i < 2; i++)
                wmma::load_matrix_sync(fa[i], Ab + (wm * 32 + i * 16) * AS_LD + kk * 8, AS_LD);
#pragma unroll
            for (int j = 0; j < 4; j++)
                wmma::load_matrix_sync(fb[j], Bb + (kk * 8) * BS_LD + wn * 64 + j * 16, BS_LD);
#pragma unroll
            for (int i = 0; i < 2; i++)
#pragma unroll
                for (int j = 0; j < 4; j++)
                    wmma::mma_sync(acc[i][j], fa[i], fb[j], acc[i][j]);
        }
        __syncthreads();
    }
#pragma unroll
    for (int i = 0; i < 2; i++)
#pragma unroll
        for (int j = 0; j < 4; j++)
            wmma::store_matrix_sync(C + (size_t)(m0 + wm * 32 + i * 16) * kF + wn * 64 + j * 16,
                                    acc[i][j], kF, wmma::mem_row_major);

    // ---- epilogue: el/er for this block's 128 rows (C tile is L1-hot) ----
    __syncthreads();
    if (t < 128) {
        int gr = m0 + t;
        if (gr < kN) {
            const float* crow = C + (size_t)gr * kF;
            const float* alr = al + r * kH * kD;
            const float* arr = ar + r * kH * kD;
#pragma unroll
            for (int h = 0; h < kH; h++) {
                float sl = 0.f, sr = 0.f;
#pragma unroll
                for (int d = 0; d < kD; d += 4) {
                    float4 f  = *(const float4*)(crow + h * kD + d);
                    float4 lv = *(const float4*)(alr + h * kD + d);
                    float4 rv = *(const float4*)(arr + h * kD + d);
                    sl += f.x * lv.x + f.y * lv.y + f.z * lv.z + f.w * lv.w;
                    sr += f.x * rv.x + f.y * rv.y + f.z * rv.z + f.w * rv.w;
                }
                g_el[((size_t)r * kN + gr) * kH + h] = sl;
                g_er[((size_t)r * kN + gr) * kH + h] = sr;
            }
        }
    }
}

// ---------------- aggregate (CSR, fused softmax): one warp per node ----------
// Writes g_h tf32-rounded so layer-2 GEMM needs no conversion.
__global__ __launch_bounds__(256) void aggregate_kernel(
    const float* __restrict__ b, int do_relu) {
    int gid = blockIdx.x * blockDim.x + threadIdx.x;
    int n = gid >> 5;
    int lane = gid & 31;
    if (n >= kN) return;
    int h = lane >> 3;
    int col = lane * 4;
    float4 tot = make_float4(0.f, 0.f, 0.f, 0.f);
#pragma unroll
    for (int r = 0; r < kR; r++) {
        int base = g_rowptr[r * kN + n];
        int deg  = g_hist[r * kN + n];
        if (deg == 0) continue;
        float erh = g_er[((size_t)r * kN + n) * kH + h];
        const float* featr = g_feat + (size_t)r * kNpad * kF;
        const float* elp = g_el + (size_t)r * kN * kH;
        const int* srcs = g_edge + (size_t)r * kE + base;
        float4 acc = make_float4(0.f, 0.f, 0.f, 0.f);
        float dsum = 0.f;
        int k = 0;
        for (; k + 4 <= deg; k += 4) {
            int s0 = srcs[k + 0], s1 = srcs[k + 1], s2 = srcs[k + 2], s3 = srcs[k + 3];
            float e0 = elp[(size_t)s0 * kH + h];
            float e1 = elp[(size_t)s1 * kH + h];
            float e2 = elp[(size_t)s2 * kH + h];
            float e3 = elp[(size_t)s3 * kH + h];
            float4 f0 = *(const float4*)(featr + (size_t)s0 * kF + col);
            float4 f1 = *(const float4*)(featr + (size_t)s1 * kF + col);
            float4 f2 = *(const float4*)(featr + (size_t)s2 * kF + col);
            float4 f3 = *(const float4*)(featr + (size_t)s3 * kF + col);
            e0 += erh; e0 = (e0 >= 0.f) ? e0 : 0.2f * e0; float x0 = __expf(e0);
            e1 += erh; e1 = (e1 >= 0.f) ? e1 : 0.2f * e1; float x1 = __expf(e1);
            e2 += erh; e2 = (e2 >= 0.f) ? e2 : 0.2f * e2; float x2 = __expf(e2);
            e3 += erh; e3 = (e3 >= 0.f) ? e3 : 0.2f * e3; float x3 = __expf(e3);
            acc.x += f0.x * x0 + f1.x * x1 + f2.x * x2 + f3.x * x3;
            acc.y += f0.y * x0 + f1.y * x1 + f2.y * x2 + f3.y * x3;
            acc.z += f0.z * x0 + f1.z * x1 + f2.z * x2 + f3.z * x3;
            acc.w += f0.w * x0 + f1.w * x1 + f2.w * x2 + f3.w * x3;
            dsum += x0 + x1 + x2 + x3;
        }
        for (; k < deg; k++) {
            int s = srcs[k];
            float e = elp[(size_t)s * kH + h] + erh;
            e = (e >= 0.f) ? e : 0.2f * e;
            float ex = __expf(e);
            float4 f = *(const float4*)(featr + (size_t)s * kF + col);
            acc.x += f.x * ex; acc.y += f.y * ex;
            acc.z += f.z * ex; acc.w += f.w * ex;
            dsum += ex;
        }
        float inv = 1.f / dsum;
        tot.x += acc.x * inv; tot.y += acc.y * inv;
        tot.z += acc.z * inv; tot.w += acc.w * inv;
    }
    int c4 = lane * 4;
    float4 b0 = *(const float4*)(b + c4);
    float4 b1 = *(const float4*)(b + kF + c4);
    float4 b2 = *(const float4*)(b + 2 * kF + c4);
    tot.x += b0.x + b1.x + b2.x;
    tot.y += b0.y + b1.y + b2.y;
    tot.z += b0.z + b1.z + b2.z;
    tot.w += b0.w + b1.w + b2.w;
    if (do_relu) {
        tot.x = fmaxf(tot.x, 0.f); tot.y = fmaxf(tot.y, 0.f);
        tot.z = fmaxf(tot.z, 0.f); tot.w = fmaxf(tot.w, 0.f);
    }
    // round to tf32 so layer-2 GEMM consumes pre-rounded data
    tot.x = wmma::__float_to_tf32(tot.x); tot.y = wmma::__float_to_tf32(tot.y);
    tot.z = wmma::__float_to_tf32(tot.z); tot.w = wmma::__float_to_tf32(tot.w);
    *(float4*)(g_h + (size_t)n * kF + c4) = tot;
}

// ---------------- final GEMM: out = g_h(N,128) @ Wl(128,64) + bl -------------
__global__ __launch_bounds__(256) void gemm_out_kernel(
    const float* __restrict__ A, const float* __restrict__ B,
    const float* __restrict__ bl, float* __restrict__ C) {
    int m0 = blockIdx.x * 128;
    __shared__ float As[8][128];
    __shared__ float Bs[8][64];
    int t = threadIdx.x;
    int ty = t >> 4;
    int tx = t & 15;
    float acc[8][4];
#pragma unroll
    for (int i = 0; i < 8; i++)
#pragma unroll
        for (int j = 0; j < 4; j++) acc[i][j] = 0.f;

    for (int k0 = 0; k0 < kF; k0 += 8) {
        {
            int row = t >> 1;
            int seg = (t & 1) * 4;
            int gr = m0 + row;
            float4 a4 = make_float4(0.f, 0.f, 0.f, 0.f);
            if (gr < kN) a4 = *(const float4*)(A + (size_t)gr * kF + k0 + seg);
            As[seg + 0][row] = a4.x; As[seg + 1][row] = a4.y;
            As[seg + 2][row] = a4.z; As[seg + 3][row] = a4.w;
            if (t < 128) {
                int brow = t >> 4;
                int bcol = (t & 15) * 4;
                *(float4*)(&Bs[brow][bcol]) = *(const float4*)(B + (size_t)(k0 + brow) * kOUT + bcol);
            }
        }
        __syncthreads();
#pragma unroll
        for (int kk = 0; kk < 8; kk++) {
            float ra[8], rb[4];
#pragma unroll
            for (int i = 0; i < 8; i++) ra[i] = As[kk][ty * 8 + i];
#pragma unroll
            for (int j = 0; j < 4; j++) rb[j] = Bs[kk][tx * 4 + j];
#pragma unroll
            for (int i = 0; i < 8; i++)
#pragma unroll
                for (int j = 0; j < 4; j++) acc[i][j] += ra[i] * rb[j];
        }
        __syncthreads();
    }
#pragma unroll
    for (int i = 0; i < 8; i++) {
        int gr = m0 + ty * 8 + i;
        if (gr < kN) {
            float4 v = make_float4(acc[i][0] + bl[tx * 4 + 0], acc[i][1] + bl[tx * 4 + 1],
                                   acc[i][2] + bl[tx * 4 + 2], acc[i][3] + bl[tx * 4 + 3]);
            *(float4*)(C + (size_t)gr * kOUT + tx * 4) = v;
        }
    }
}

extern "C" void kernel_launch(void* const* d_in, const int* in_sizes, int n_in,
                              void* d_out, int out_size) {
    const float* x     = (const float*)d_in[0];
    const int*   edges = (const int*)d_in[1];   // JAX x64 disabled -> int32
    const float* W1    = (const float*)d_in[2];
    const float* al1   = (const float*)d_in[3];
    const float* ar1   = (const float*)d_in[4];
    const float* b1    = (const float*)d_in[5];
    const float* W2    = (const float*)d_in[6];
    const float* al2   = (const float*)d_in[7];
    const float* ar2   = (const float*)d_in[8];
    const float* b2    = (const float*)d_in[9];
    const float* Wl    = (const float*)d_in[10];
    const float* bl    = (const float*)d_in[11];
    float*       out   = (float*)d_out;

    float *hbuf = nullptr, *xtf = nullptr, *wtf = nullptr;
    cudaGetSymbolAddress((void**)&hbuf, g_h);
    cudaGetSymbolAddress((void**)&xtf, g_xtf);
    cudaGetSymbolAddress((void**)&wtf, g_wtf);

    const int TB = 256;
    const int GEMM_SMEM = (2 * 128 * AS_LD + 2 * 32 * BS_LD) * 4;  // 70656 B
    static int attr_set = 0;
    if (!attr_set) {
        cudaFuncSetAttribute(gemm_feat_tc, cudaFuncAttributeMaxDynamicSharedMemorySize, GEMM_SMEM);
        attr_set = 1;
    }
    dim3 gemm_grid((kN + 127) / 128, 1, kR);

    // 0,1: pre-round W and x to tf32
    cvt_w_kernel<<<(2 * kR * kF * kF + TB - 1) / TB, TB>>>(W1, W2);
    cvt_x_kernel<<<(kN * kF / 4 + TB - 1) / TB, TB>>>(x);
    // 2: zero hist
    zero_hist_kernel<<<(kR * kN + TB - 1) / TB, TB>>>();
    // 3: layer-1 GEMM (profiled slot)
    gemm_feat_tc<<<gemm_grid, TB, GEMM_SMEM>>>(xtf, wtf, al1, ar1);
    // 4-6: CSR build
    hist_kernel<<<(kR * kE + TB - 1) / TB, TB>>>(edges);
    scan_kernel<<<kR, 1024>>>();
    scatter_kernel<<<(kR * kE + TB - 1) / TB, TB>>>(edges);
    // 7: layer-1 aggregate
    aggregate_kernel<<<(kN * 32 + TB - 1) / TB, TB>>>(b1, 1);
    // 8-9: layer 2
    gemm_feat_tc<<<gemm_grid, TB, GEMM_SMEM>>>(hbuf, wtf + kR * kF * kF, al2, ar2);
    aggregate_kernel<<<(kN * 32 + TB - 1) / TB, TB>>>(b2, 0);
    // 10: final linear
    gemm_out_kernel<<<(kN + 127) / 128, TB>>>(hbuf, Wl, bl, out);
}

// round 16
// speedup vs baseline: 1.7930x; 1.7930x over previous
#include <cuda_runtime.h>
#include <cstdint>
#include <mma.h>
using namespace nvcuda;

// Problem constants
#define kN 50000
#define kNpad 50176   // padded per-relation row stride
#define kR 3
#define kE 300000
#define kH 4
#define kD 32
#define kF 128
#define kOUT 64

// ---------------- scratch (device globals; no allocations allowed) ----------
__device__ __align__(16) float g_feat[(size_t)kR * kNpad * kF];  // projected features
__device__ __align__(16) float g_el[(size_t)kR * kN * kH];
__device__ __align__(16) float g_er[(size_t)kR * kN * kH];
__device__ __align__(16) float g_h[(size_t)kN * kF];             // layer outputs (tf32-rounded)
__device__ __align__(16) float g_xtf[(size_t)kN * kF];           // tf32-rounded input x
__device__ __align__(16) float g_wtf[2 * kR * kF * kF];          // tf32-rounded W1|W2
// CSR (built once per launch; edges shared by both layers)
__device__ int g_hist[kR * kN];
__device__ int g_rowptr[kR * kN];
__device__ int g_cursor[kR * kN];
__device__ int g_edge[(size_t)kR * kE];  // src node ids, grouped by dst

// ---------------- pre-conversion kernels (round to tf32 once) ---------------
__global__ void cvt_w_kernel(const float* __restrict__ W1, const float* __restrict__ W2) {
    int i = blockIdx.x * blockDim.x + threadIdx.x;
    const int nw = kR * kF * kF;
    if (i < nw)          g_wtf[i] = wmma::__float_to_tf32(W1[i]);
    else if (i < 2 * nw) g_wtf[i] = wmma::__float_to_tf32(W2[i - nw]);
}
__global__ void cvt_x_kernel(const float* __restrict__ x) {
    int i = blockIdx.x * blockDim.x + threadIdx.x;
    if (i >= kN * kF / 4) return;
    float4 v = ((const float4*)x)[i];
    v.x = wmma::__float_to_tf32(v.x); v.y = wmma::__float_to_tf32(v.y);
    v.z = wmma::__float_to_tf32(v.z); v.w = wmma::__float_to_tf32(v.w);
    ((float4*)g_xtf)[i] = v;
}

// ---------------- zero hist --------------------------------------------------
__global__ void zero_hist_kernel() {
    int idx = blockIdx.x * blockDim.x + threadIdx.x;
    if (idx < kR * kN) g_hist[idx] = 0;
}

// ---------------- CSR build --------------------------------------------------
__global__ void hist_kernel(const int* __restrict__ edges) {
    int idx = blockIdx.x * blockDim.x + threadIdx.x;
    if (idx >= kR * kE) return;
    int r = idx / kE, e = idx % kE;
    int dst = edges[(size_t)r * 2 * kE + kE + e];
    atomicAdd(&g_hist[r * kN + dst], 1);
}

__global__ __launch_bounds__(1024) void scan_kernel() {
    __shared__ int sums[1024];
    int r = blockIdx.x;
    int t = threadIdx.x;
    const int CH = (kN + 1023) / 1024;  // 49
    int begin = t * CH;
    int end = min(begin + CH, kN);
    int s = 0;
    for (int i = begin; i < end; i++) s += g_hist[r * kN + i];
    sums[t] = s;
    __syncthreads();
    for (int off = 1; off < 1024; off <<= 1) {
        int v = (t >= off) ? sums[t - off] : 0;
        __syncthreads();
        sums[t] += v;
        __syncthreads();
    }
    int running = sums[t] - s;  // exclusive
    for (int i = begin; i < end; i++) {
        g_rowptr[r * kN + i] = running;
        g_cursor[r * kN + i] = running;
        running += g_hist[r * kN + i];
    }
}

__global__ void scatter_kernel(const int* __restrict__ edges) {
    int idx = blockIdx.x * blockDim.x + threadIdx.x;
    if (idx >= kR * kE) return;
    int r = idx / kE, e = idx % kE;
    const int* eb = edges + (size_t)r * 2 * kE;
    int src = eb[e];
    int dst = eb[kE + e];
    int pos = atomicAdd(&g_cursor[r * kN + dst], 1);
    g_edge[(size_t)r * kE + pos] = src;
}

// ---------------- GEMM (tf32 WMMA, BM=128, LDG->reg->STS double buffer) -----
// Pre-rounded inputs (no CVTs). acc[2][4] = 64 regs. 2 CTAs/SM forced.
#define AS_LD 36
#define BS_LD 132
__global__ __launch_bounds__(256, 2) void gemm_feat_tc(
    const float* __restrict__ A, const float* __restrict__ W,
    const float* __restrict__ al, const float* __restrict__ ar) {
    extern __shared__ float smem[];
    float* As = smem;                      // [2][128][AS_LD]
    float* Bs = smem + 2 * 128 * AS_LD;    // [2][32][BS_LD]

    int r = blockIdx.z;
    int m0 = blockIdx.x * 128;
    const float* B = W + (size_t)r * kF * kF;
    float* C = g_feat + (size_t)r * kNpad * kF;

    int t = threadIdx.x;
    int w = t >> 5;
    int wm = w & 3;        // 32-row slab
    int wn = w >> 2;       // 64-col slab

    // per-thread staging coordinates (fixed across chunks)
    int a_rr = t >> 1;                 // A: 2 float4 per thread -> rows t/2
    int a_cc = (t & 1) * 16;           // two 16-float halves? no: use 4x loop below
    (void)a_rr; (void)a_cc;

    // ---- stage chunk 0 (LDG -> STS, L1-cached) ----
#pragma unroll
    for (int g = 0; g < 4; g++) {                  // A: 128x32 = 1024 float4
        int lin = g * 256 + t;
        int rr = lin >> 3;
        int cc = (lin & 7) * 4;
        int gr = m0 + rr;
        float4 v = make_float4(0.f, 0.f, 0.f, 0.f);
        if (gr < kN) v = *(const float4*)(A + (size_t)gr * kF + cc);
        *(float4*)&As[rr * AS_LD + cc] = v;
    }
#pragma unroll
    for (int g = 0; g < 4; g++) {                  // B: 32x128 = 1024 float4
        int lin = g * 256 + t;
        int row = lin >> 5;
        int col = (lin & 31) * 4;
        *(float4*)&Bs[row * BS_LD + col] = *(const float4*)(B + (size_t)row * kF + col);
    }
    __syncthreads();

    wmma::fragment<wmma::accumulator, 16, 16, 8, float> acc[2][4];
#pragma unroll
    for (int i = 0; i < 2; i++)
#pragma unroll
        for (int j = 0; j < 4; j++) wmma::fill_fragment(acc[i][j], 0.f);

#pragma unroll
    for (int c = 0; c < 4; c++) {
        // prefetch next chunk into registers (issued before compute for overlap)
        float4 pa[4], pb[4];
        if (c < 3) {
#pragma unroll
            for (int g = 0; g < 4; g++) {
                int lin = g * 256 + t;
                int rr = lin >> 3;
                int cc = (lin & 7) * 4;
                int gr = m0 + rr;
                float4 v = make_float4(0.f, 0.f, 0.f, 0.f);
                if (gr < kN) v = *(const float4*)(A + (size_t)gr * kF + (c + 1) * 32 + cc);
                pa[g] = v;
            }
#pragma unroll
            for (int g = 0; g < 4; g++) {
                int lin = g * 256 + t;
                int row = lin >> 5;
                int col = (lin & 31) * 4;
                pb[g] = *(const float4*)(B + (size_t)((c + 1) * 32 + row) * kF + col);
            }
        }
        // compute on current buffer
        const float* Ab = As + (c & 1) * 128 * AS_LD;
        const float* Bb = Bs + (c & 1) * 32 * BS_LD;
#pragma unroll
        for (int kk = 0; kk < 4; kk++) {
            wmma::fragment<wmma::matrix_a, 16, 16, 8, wmma::precision::tf32, wmma::row_major> fa[2];
            wmma::fragment<wmma::matrix_b, 16, 16, 8, wmma::precision::tf32, wmma::row_major> fb[4];
#pragma unroll
            for (int i = 0; i < 2; i++)
                wmma::load_matrix_sync(fa[i], Ab + (wm * 32 + i * 16) * AS_LD + kk * 8, AS_LD);
#pragma unroll
            for (int j = 0; j < 4; j++)
                wmma::load_matrix_sync(fb[j], Bb + (kk * 8) * BS_LD + wn * 64 + j * 16, BS_LD);
#pragma unroll
            for (int i = 0; i < 2; i++)
#pragma unroll
                for (int j = 0; j < 4; j++)
                    wmma::mma_sync(acc[i][j], fa[i], fb[j], acc[i][j]);
        }
        // store prefetched chunk into the other buffer
        if (c < 3) {
            float* Anb = As + ((c + 1) & 1) * 128 * AS_LD;
            float* Bnb = Bs + ((c + 1) & 1) * 32 * BS_LD;
#pragma unroll
            for (int g = 0; g < 4; g++) {
                int lin = g * 256 + t;
                int rr = lin >> 3;
                int cc = (lin & 7) * 4;
                *(float4*)&Anb[rr * AS_LD + cc] = pa[g];
            }
#pragma unroll
            for (int g = 0; g < 4; g++) {
                int lin = g * 256 + t;
                int row = lin >> 5;
                int col = (lin & 31) * 4;
                *(float4*)&Bnb[row * BS_LD + col] = pb[g];
            }
            __syncthreads();
        }
    }
#pragma unroll
    for (int i = 0; i < 2; i++)
#pragma unroll
        for (int j = 0; j < 4; j++)
            wmma::store_matrix_sync(C + (size_t)(m0 + wm * 32 + i * 16) * kF + wn * 64 + j * 16,
                                    acc[i][j], kF, wmma::mem_row_major);

    // ---- epilogue: el/er for this block's 128 rows (C tile is L1-hot) ----
    __syncthreads();
    if (t < 128) {
        int gr = m0 + t;
        if (gr < kN) {
            const float* crow = C + (size_t)gr * kF;
            const float* alr = al + r * kH * kD;
            const float* arr = ar + r * kH * kD;
#pragma unroll
            for (int h = 0; h < kH; h++) {
                float sl = 0.f, sr = 0.f;
#pragma unroll
                for (int d = 0; d < kD; d += 4) {
                    float4 f  = *(const float4*)(crow + h * kD + d);
                    float4 lv = *(const float4*)(alr + h * kD + d);
                    float4 rv = *(const float4*)(arr + h * kD + d);
                    sl += f.x * lv.x + f.y * lv.y + f.z * lv.z + f.w * lv.w;
                    sr += f.x * rv.x + f.y * rv.y + f.z * rv.z + f.w * rv.w;
                }
                g_el[((size_t)r * kN + gr) * kH + h] = sl;
                g_er[((size_t)r * kN + gr) * kH + h] = sr;
            }
        }
    }
}

// ---------------- aggregate (CSR, fused softmax): one warp per node ----------
__global__ __launch_bounds__(256) void aggregate_kernel(
    const float* __restrict__ b, int do_relu) {
    int gid = blockIdx.x * blockDim.x + threadIdx.x;
    int n = gid >> 5;
    int lane = gid & 31;
    if (n >= kN) return;
    int h = lane >> 3;
    int col = lane * 4;
    float4 tot = make_float4(0.f, 0.f, 0.f, 0.f);
#pragma unroll
    for (int r = 0; r < kR; r++) {
        int base = g_rowptr[r * kN + n];
        int deg  = g_hist[r * kN + n];
        if (deg == 0) continue;
        float erh = g_er[((size_t)r * kN + n) * kH + h];
        const float* featr = g_feat + (size_t)r * kNpad * kF;
        const float* elp = g_el + (size_t)r * kN * kH;
        const int* srcs = g_edge + (size_t)r * kE + base;
        float4 acc = make_float4(0.f, 0.f, 0.f, 0.f);
        float dsum = 0.f;
        int k = 0;
        for (; k + 4 <= deg; k += 4) {
            int s0 = srcs[k + 0], s1 = srcs[k + 1], s2 = srcs[k + 2], s3 = srcs[k + 3];
            float e0 = elp[(size_t)s0 * kH + h];
            float e1 = elp[(size_t)s1 * kH + h];
            float e2 = elp[(size_t)s2 * kH + h];
            float e3 = elp[(size_t)s3 * kH + h];
            float4 f0 = *(const float4*)(featr + (size_t)s0 * kF + col);
            float4 f1 = *(const float4*)(featr + (size_t)s1 * kF + col);
            float4 f2 = *(const float4*)(featr + (size_t)s2 * kF + col);
            float4 f3 = *(const float4*)(featr + (size_t)s3 * kF + col);
            e0 += erh; e0 = (e0 >= 0.f) ? e0 : 0.2f * e0; float x0 = __expf(e0);
            e1 += erh; e1 = (e1 >= 0.f) ? e1 : 0.2f * e1; float x1 = __expf(e1);
            e2 += erh; e2 = (e2 >= 0.f) ? e2 : 0.2f * e2; float x2 = __expf(e2);
            e3 += erh; e3 = (e3 >= 0.f) ? e3 : 0.2f * e3; float x3 = __expf(e3);
            acc.x += f0.x * x0 + f1.x * x1 + f2.x * x2 + f3.x * x3;
            acc.y += f0.y * x0 + f1.y * x1 + f2.y * x2 + f3.y * x3;
            acc.z += f0.z * x0 + f1.z * x1 + f2.z * x2 + f3.z * x3;
            acc.w += f0.w * x0 + f1.w * x1 + f2.w * x2 + f3.w * x3;
            dsum += x0 + x1 + x2 + x3;
        }
        for (; k < deg; k++) {
            int s = srcs[k];
            float e = elp[(size_t)s * kH + h] + erh;
            e = (e >= 0.f) ? e : 0.2f * e;
            float ex = __expf(e);
            float4 f = *(const float4*)(featr + (size_t)s * kF + col);
            acc.x += f.x * ex; acc.y += f.y * ex;
            acc.z += f.z * ex; acc.w += f.w * ex;
            dsum += ex;
        }
        float inv = 1.f / dsum;
        tot.x += acc.x * inv; tot.y += acc.y * inv;
        tot.z += acc.z * inv; tot.w += acc.w * inv;
    }
    int c4 = lane * 4;
    float4 b0 = *(const float4*)(b + c4);
    float4 b1 = *(const float4*)(b + kF + c4);
    float4 b2 = *(const float4*)(b + 2 * kF + c4);
    tot.x += b0.x + b1.x + b2.x;
    tot.y += b0.y + b1.y + b2.y;
    tot.z += b0.z + b1.z + b2.z;
    tot.w += b0.w + b1.w + b2.w;
    if (do_relu) {
        tot.x = fmaxf(tot.x, 0.f); tot.y = fmaxf(tot.y, 0.f);
        tot.z = fmaxf(tot.z, 0.f); tot.w = fmaxf(tot.w, 0.f);
    }
    // round to tf32 so layer-2 GEMM consumes pre-rounded data
    tot.x = wmma::__float_to_tf32(tot.x); tot.y = wmma::__float_to_tf32(tot.y);
    tot.z = wmma::__float_to_tf32(tot.z); tot.w = wmma::__float_to_tf32(tot.w);
    *(float4*)(g_h + (size_t)n * kF + c4) = tot;
}

// ---------------- final GEMM: out = g_h(N,128) @ Wl(128,64) + bl -------------
__global__ __launch_bounds__(256) void gemm_out_kernel(
    const float* __restrict__ A, const float* __restrict__ B,
    const float* __restrict__ bl, float* __restrict__ C) {
    int m0 = blockIdx.x * 128;
    __shared__ float As[8][128];
    __shared__ float Bs[8][64];
    int t = threadIdx.x;
    int ty = t >> 4;
    int tx = t & 15;
    float acc[8][4];
#pragma unroll
    for (int i = 0; i < 8; i++)
#pragma unroll
        for (int j = 0; j < 4; j++) acc[i][j] = 0.f;

    for (int k0 = 0; k0 < kF; k0 += 8) {
        {
            int row = t >> 1;
            int seg = (t & 1) * 4;
            int gr = m0 + row;
            float4 a4 = make_float4(0.f, 0.f, 0.f, 0.f);
            if (gr < kN) a4 = *(const float4*)(A + (size_t)gr * kF + k0 + seg);
            As[seg + 0][row] = a4.x; As[seg + 1][row] = a4.y;
            As[seg + 2][row] = a4.z; As[seg + 3][row] = a4.w;
            if (t < 128) {
                int brow = t >> 4;
                int bcol = (t & 15) * 4;
                *(float4*)(&Bs[brow][bcol]) = *(const float4*)(B + (size_t)(k0 + brow) * kOUT + bcol);
            }
        }
        __syncthreads();
#pragma unroll
        for (int kk = 0; kk < 8; kk++) {
            float ra[8], rb[4];
#pragma unroll
            for (int i = 0; i < 8; i++) ra[i] = As[kk][ty * 8 + i];
#pragma unroll
            for (int j = 0; j < 4; j++) rb[j] = Bs[kk][tx * 4 + j];
#pragma unroll
            for (int i = 0; i < 8; i++)
#pragma unroll
                for (int j = 0; j < 4; j++) acc[i][j] += ra[i] * rb[j];
        }
        __syncthreads();
    }
#pragma unroll
    for (int i = 0; i < 8; i++) {
        int gr = m0 + ty * 8 + i;
        if (gr < kN) {
            float4 v = make_float4(acc[i][0] + bl[tx * 4 + 0], acc[i][1] + bl[tx * 4 + 1],
                                   acc[i][2] + bl[tx * 4 + 2], acc[i][3] + bl[tx * 4 + 3]);
            *(float4*)(C + (size_t)gr * kOUT + tx * 4) = v;
        }
    }
}

extern "C" void kernel_launch(void* const* d_in, const int* in_sizes, int n_in,
                              void* d_out, int out_size) {
    const float* x     = (const float*)d_in[0];
    const int*   edges = (const int*)d_in[1];   // JAX x64 disabled -> int32
    const float* W1    = (const float*)d_in[2];
    const float* al1   = (const float*)d_in[3];
    const float* ar1   = (const float*)d_in[4];
    const float* b1    = (const float*)d_in[5];
    const float* W2    = (const float*)d_in[6];
    const float* al2   = (const float*)d_in[7];
    const float* ar2   = (const float*)d_in[8];
    const float* b2    = (const float*)d_in[9];
    const float* Wl    = (const float*)d_in[10];
    const float* bl    = (const float*)d_in[11];
    float*       out   = (float*)d_out;

    float *hbuf = nullptr, *xtf = nullptr, *wtf = nullptr;
    cudaGetSymbolAddress((void**)&hbuf, g_h);
    cudaGetSymbolAddress((void**)&xtf, g_xtf);
    cudaGetSymbolAddress((void**)&wtf, g_wtf);

    const int TB = 256;
    const int GEMM_SMEM = (2 * 128 * AS_LD + 2 * 32 * BS_LD) * 4;  // 70656 B
    static int attr_set = 0;
    if (!attr_set) {
        cudaFuncSetAttribute(gemm_feat_tc, cudaFuncAttributeMaxDynamicSharedMemorySize, GEMM_SMEM);
        attr_set = 1;
    }
    dim3 gemm_grid((kN + 127) / 128, 1, kR);

    // 0,1: pre-round W and x to tf32
    cvt_w_kernel<<<(2 * kR * kF * kF + TB - 1) / TB, TB>>>(W1, W2);
    cvt_x_kernel<<<(kN * kF / 4 + TB - 1) / TB, TB>>>(x);
    // 2: zero hist
    zero_hist_kernel<<<(kR * kN + TB - 1) / TB, TB>>>();
    // 3: layer-1 GEMM
    gemm_feat_tc<<<gemm_grid, TB, GEMM_SMEM>>>(xtf, wtf, al1, ar1);
    // 4-6: CSR build
    hist_kernel<<<(kR * kE + TB - 1) / TB, TB>>>(edges);
    scan_kernel<<<kR, 1024>>>();
    scatter_kernel<<<(kR * kE + TB - 1) / TB, TB>>>(edges);
    // 7: layer-1 aggregate
    aggregate_kernel<<<(kN * 32 + TB - 1) / TB, TB>>>(b1, 1);
    // 8-9: layer 2
    gemm_feat_tc<<<gemm_grid, TB, GEMM_SMEM>>>(hbuf, wtf + kR * kF * kF, al2, ar2);
    aggregate_kernel<<<(kN * 32 + TB - 1) / TB, TB>>>(b2, 0);
    // 10: final linear
    gemm_out_kernel<<<(kN + 127) / 128, TB>>>(hbuf, Wl, bl, out);
}

// round 17
// speedup vs baseline: 1.7966x; 1.0020x over previous
#include <cuda_runtime.h>
#include <cstdint>
#include <mma.h>
using namespace nvcuda;

// Problem constants
#define kN 50000
#define kNpad 50176   // padded per-relation row stride
#define kR 3
#define kE 300000
#define kH 4
#define kD 32
#define kF 128
#define kOUT 64

// ---------------- scratch (device globals; no allocations allowed) ----------
__device__ __align__(16) float g_feat[(size_t)kR * kNpad * kF];  // projected features
__device__ __align__(16) float g_el[(size_t)kR * kN * kH];
__device__ __align__(16) float g_er[(size_t)kR * kN * kH];
__device__ __align__(16) float g_h[(size_t)kN * kF];             // layer outputs (tf32-rounded)
__device__ __align__(16) float g_xtf[(size_t)kN * kF];           // tf32-rounded input x
__device__ __align__(16) float g_wtf[2 * kR * kF * kF];          // tf32-rounded W1|W2
// CSR (built once per launch; edges shared by both layers)
__device__ int g_hist[kR * kN];
__device__ int g_rowptr[kR * kN];
__device__ int g_cursor[kR * kN];
__device__ int g_edge[(size_t)kR * kE];  // src node ids, grouped by dst

// ---------------- pre-conversion kernels (round to tf32 once) ---------------
__global__ void cvt_w_kernel(const float* __restrict__ W1, const float* __restrict__ W2) {
    int i = blockIdx.x * blockDim.x + threadIdx.x;
    const int nw = kR * kF * kF;
    if (i < nw)          g_wtf[i] = wmma::__float_to_tf32(W1[i]);
    else if (i < 2 * nw) g_wtf[i] = wmma::__float_to_tf32(W2[i - nw]);
}
__global__ void cvt_x_kernel(const float* __restrict__ x) {
    int i = blockIdx.x * blockDim.x + threadIdx.x;
    if (i >= kN * kF / 4) return;
    float4 v = ((const float4*)x)[i];
    v.x = wmma::__float_to_tf32(v.x); v.y = wmma::__float_to_tf32(v.y);
    v.z = wmma::__float_to_tf32(v.z); v.w = wmma::__float_to_tf32(v.w);
    ((float4*)g_xtf)[i] = v;
}

// ---------------- zero hist --------------------------------------------------
__global__ void zero_hist_kernel() {
    int idx = blockIdx.x * blockDim.x + threadIdx.x;
    if (idx < kR * kN) g_hist[idx] = 0;
}

// ---------------- CSR build --------------------------------------------------
__global__ void hist_kernel(const int* __restrict__ edges) {
    int idx = blockIdx.x * blockDim.x + threadIdx.x;
    if (idx >= kR * kE) return;
    int r = idx / kE, e = idx % kE;
    int dst = edges[(size_t)r * 2 * kE + kE + e];
    atomicAdd(&g_hist[r * kN + dst], 1);
}

__global__ __launch_bounds__(1024) void scan_kernel() {
    __shared__ int sums[1024];
    int r = blockIdx.x;
    int t = threadIdx.x;
    const int CH = (kN + 1023) / 1024;  // 49
    int begin = t * CH;
    int end = min(begin + CH, kN);
    int s = 0;
    for (int i = begin; i < end; i++) s += g_hist[r * kN + i];
    sums[t] = s;
    __syncthreads();
    for (int off = 1; off < 1024; off <<= 1) {
        int v = (t >= off) ? sums[t - off] : 0;
        __syncthreads();
        sums[t] += v;
        __syncthreads();
    }
    int running = sums[t] - s;  // exclusive
    for (int i = begin; i < end; i++) {
        g_rowptr[r * kN + i] = running;
        g_cursor[r * kN + i] = running;
        running += g_hist[r * kN + i];
    }
}

__global__ void scatter_kernel(const int* __restrict__ edges) {
    int idx = blockIdx.x * blockDim.x + threadIdx.x;
    if (idx >= kR * kE) return;
    int r = idx / kE, e = idx % kE;
    const int* eb = edges + (size_t)r * 2 * kE;
    int src = eb[e];
    int dst = eb[kE + e];
    int pos = atomicAdd(&g_cursor[r * kN + dst], 1);
    g_edge[(size_t)r * kE + pos] = src;
}

// ---------------- GEMM (tf32 WMMA, BM=128, LDG->reg->STS double buffer) -----
// Pre-rounded inputs (no CVTs). acc[2][4] = 64 regs. 2 CTAs/SM forced.
// UNCHANGED from R16 (measured 98us, control for this round).
#define AS_LD 36
#define BS_LD 132
__global__ __launch_bounds__(256, 2) void gemm_feat_tc(
    const float* __restrict__ A, const float* __restrict__ W,
    const float* __restrict__ al, const float* __restrict__ ar) {
    extern __shared__ float smem[];
    float* As = smem;                      // [2][128][AS_LD]
    float* Bs = smem + 2 * 128 * AS_LD;    // [2][32][BS_LD]

    int r = blockIdx.z;
    int m0 = blockIdx.x * 128;
    const float* B = W + (size_t)r * kF * kF;
    float* C = g_feat + (size_t)r * kNpad * kF;

    int t = threadIdx.x;
    int w = t >> 5;
    int wm = w & 3;        // 32-row slab
    int wn = w >> 2;       // 64-col slab

    // ---- stage chunk 0 (LDG -> STS, L1-cached) ----
#pragma unroll
    for (int g = 0; g < 4; g++) {                  // A: 128x32 = 1024 float4
        int lin = g * 256 + t;
        int rr = lin >> 3;
        int cc = (lin & 7) * 4;
        int gr = m0 + rr;
        float4 v = make_float4(0.f, 0.f, 0.f, 0.f);
        if (gr < kN) v = *(const float4*)(A + (size_t)gr * kF + cc);
        *(float4*)&As[rr * AS_LD + cc] = v;
    }
#pragma unroll
    for (int g = 0; g < 4; g++) {                  // B: 32x128 = 1024 float4
        int lin = g * 256 + t;
        int row = lin >> 5;
        int col = (lin & 31) * 4;
        *(float4*)&Bs[row * BS_LD + col] = *(const float4*)(B + (size_t)row * kF + col);
    }
    __syncthreads();

    wmma::fragment<wmma::accumulator, 16, 16, 8, float> acc[2][4];
#pragma unroll
    for (int i = 0; i < 2; i++)
#pragma unroll
        for (int j = 0; j < 4; j++) wmma::fill_fragment(acc[i][j], 0.f);

#pragma unroll
    for (int c = 0; c < 4; c++) {
        // prefetch next chunk into registers (issued before compute for overlap)
        float4 pa[4], pb[4];
        if (c < 3) {
#pragma unroll
            for (int g = 0; g < 4; g++) {
                int lin = g * 256 + t;
                int rr = lin >> 3;
                int cc = (lin & 7) * 4;
                int gr = m0 + rr;
                float4 v = make_float4(0.f, 0.f, 0.f, 0.f);
                if (gr < kN) v = *(const float4*)(A + (size_t)gr * kF + (c + 1) * 32 + cc);
                pa[g] = v;
            }
#pragma unroll
            for (int g = 0; g < 4; g++) {
                int lin = g * 256 + t;
                int row = lin >> 5;
                int col = (lin & 31) * 4;
                pb[g] = *(const float4*)(B + (size_t)((c + 1) * 32 + row) * kF + col);
            }
        }
        // compute on current buffer
        const float* Ab = As + (c & 1) * 128 * AS_LD;
        const float* Bb = Bs + (c & 1) * 32 * BS_LD;
#pragma unroll
        for (int kk = 0; kk < 4; kk++) {
            wmma::fragment<wmma::matrix_a, 16, 16, 8, wmma::precision::tf32, wmma::row_major> fa[2];
            wmma::fragment<wmma::matrix_b, 16, 16, 8, wmma::precision::tf32, wmma::row_major> fb[4];
#pragma unroll
            for (int i = 0; i < 2; i++)
                wmma::load_matrix_sync(fa[i], Ab + (wm * 32 + i * 16) * AS_LD + kk * 8, AS_LD);
#pragma unroll
            for (int j = 0; j < 4; j++)
                wmma::load_matrix_sync(fb[j], Bb + (kk * 8) * BS_LD + wn * 64 + j * 16, BS_LD);
#pragma unroll
            for (int i = 0; i < 2; i++)
#pragma unroll
                for (int j = 0; j < 4; j++)
                    wmma::mma_sync(acc[i][j], fa[i], fb[j], acc[i][j]);
        }
        // store prefetched chunk into the other buffer
        if (c < 3) {
            float* Anb = As + ((c + 1) & 1) * 128 * AS_LD;
            float* Bnb = Bs + ((c + 1) & 1) * 32 * BS_LD;
#pragma unroll
            for (int g = 0; g < 4; g++) {
                int lin = g * 256 + t;
                int rr = lin >> 3;
                int cc = (lin & 7) * 4;
                *(float4*)&Anb[rr * AS_LD + cc] = pa[g];
            }
#pragma unroll
            for (int g = 0; g < 4; g++) {
                int lin = g * 256 + t;
                int row = lin >> 5;
                int col = (lin & 31) * 4;
                *(float4*)&Bnb[row * BS_LD + col] = pb[g];
            }
            __syncthreads();
        }
    }
#pragma unroll
    for (int i = 0; i < 2; i++)
#pragma unroll
        for (int j = 0; j < 4; j++)
            wmma::store_matrix_sync(C + (size_t)(m0 + wm * 32 + i * 16) * kF + wn * 64 + j * 16,
                                    acc[i][j], kF, wmma::mem_row_major);

    // ---- epilogue: el/er for this block's 128 rows (C tile is L1-hot) ----
    __syncthreads();
    if (t < 128) {
        int gr = m0 + t;
        if (gr < kN) {
            const float* crow = C + (size_t)gr * kF;
            const float* alr = al + r * kH * kD;
            const float* arr = ar + r * kH * kD;
#pragma unroll
            for (int h = 0; h < kH; h++) {
                float sl = 0.f, sr = 0.f;
#pragma unroll
                for (int d = 0; d < kD; d += 4) {
                    float4 f  = *(const float4*)(crow + h * kD + d);
                    float4 lv = *(const float4*)(alr + h * kD + d);
                    float4 rv = *(const float4*)(arr + h * kD + d);
                    sl += f.x * lv.x + f.y * lv.y + f.z * lv.z + f.w * lv.w;
                    sr += f.x * rv.x + f.y * rv.y + f.z * rv.z + f.w * rv.w;
                }
                g_el[((size_t)r * kN + gr) * kH + h] = sl;
                g_er[((size_t)r * kN + gr) * kH + h] = sr;
            }
        }
    }
}

// ---------------- aggregate (CSR, fused softmax): one warp per node ----------
// Fully predicated batch-4: ragged tail handled by index clamp + zero weight,
// so EVERY edge goes through the MLP~8 path (mean degree is only 6).
__global__ __launch_bounds__(256) void aggregate_kernel(
    const float* __restrict__ b, int do_relu) {
    int gid = blockIdx.x * blockDim.x + threadIdx.x;
    int n = gid >> 5;
    int lane = gid & 31;
    if (n >= kN) return;
    int h = lane >> 3;
    int col = lane * 4;
    float4 tot = make_float4(0.f, 0.f, 0.f, 0.f);
#pragma unroll
    for (int r = 0; r < kR; r++) {
        int base = g_rowptr[r * kN + n];
        int deg  = g_hist[r * kN + n];
        if (deg == 0) continue;
        float erh = g_er[((size_t)r * kN + n) * kH + h];
        const float* featr = g_feat + (size_t)r * kNpad * kF;
        const float* elp = g_el + (size_t)r * kN * kH;
        const int* srcs = g_edge + (size_t)r * kE + base;
        float4 acc = make_float4(0.f, 0.f, 0.f, 0.f);
        float dsum = 0.f;
        for (int k = 0; k < deg; k += 4) {
            // clamped indices: duplicates hit the same L2 lines (~free)
            int i1 = min(k + 1, deg - 1);
            int i2 = min(k + 2, deg - 1);
            int i3 = min(k + 3, deg - 1);
            int s0 = srcs[k], s1 = srcs[i1], s2 = srcs[i2], s3 = srcs[i3];
            float e0 = elp[(size_t)s0 * kH + h];
            float e1 = elp[(size_t)s1 * kH + h];
            float e2 = elp[(size_t)s2 * kH + h];
            float e3 = elp[(size_t)s3 * kH + h];
            float4 f0 = *(const float4*)(featr + (size_t)s0 * kF + col);
            float4 f1 = *(const float4*)(featr + (size_t)s1 * kF + col);
            float4 f2 = *(const float4*)(featr + (size_t)s2 * kF + col);
            float4 f3 = *(const float4*)(featr + (size_t)s3 * kF + col);
            e0 += erh; e0 = (e0 >= 0.f) ? e0 : 0.2f * e0; float x0 = __expf(e0);
            e1 += erh; e1 = (e1 >= 0.f) ? e1 : 0.2f * e1; float x1 = __expf(e1);
            e2 += erh; e2 = (e2 >= 0.f) ? e2 : 0.2f * e2; float x2 = __expf(e2);
            e3 += erh; e3 = (e3 >= 0.f) ? e3 : 0.2f * e3; float x3 = __expf(e3);
            // mask out-of-range slots (zero weight kills num & denom contributions)
            x1 = (k + 1 < deg) ? x1 : 0.f;
            x2 = (k + 2 < deg) ? x2 : 0.f;
            x3 = (k + 3 < deg) ? x3 : 0.f;
            acc.x += f0.x * x0 + f1.x * x1 + f2.x * x2 + f3.x * x3;
            acc.y += f0.y * x0 + f1.y * x1 + f2.y * x2 + f3.y * x3;
            acc.z += f0.z * x0 + f1.z * x1 + f2.z * x2 + f3.z * x3;
            acc.w += f0.w * x0 + f1.w * x1 + f2.w * x2 + f3.w * x3;
            dsum += x0 + x1 + x2 + x3;
        }
        float inv = 1.f / dsum;
        tot.x += acc.x * inv; tot.y += acc.y * inv;
        tot.z += acc.z * inv; tot.w += acc.w * inv;
    }
    int c4 = lane * 4;
    float4 b0 = *(const float4*)(b + c4);
    float4 b1 = *(const float4*)(b + kF + c4);
    float4 b2 = *(const float4*)(b + 2 * kF + c4);
    tot.x += b0.x + b1.x + b2.x;
    tot.y += b0.y + b1.y + b2.y;
    tot.z += b0.z + b1.z + b2.z;
    tot.w += b0.w + b1.w + b2.w;
    if (do_relu) {
        tot.x = fmaxf(tot.x, 0.f); tot.y = fmaxf(tot.y, 0.f);
        tot.z = fmaxf(tot.z, 0.f); tot.w = fmaxf(tot.w, 0.f);
    }
    // round to tf32 so layer-2 GEMM consumes pre-rounded data
    tot.x = wmma::__float_to_tf32(tot.x); tot.y = wmma::__float_to_tf32(tot.y);
    tot.z = wmma::__float_to_tf32(tot.z); tot.w = wmma::__float_to_tf32(tot.w);
    *(float4*)(g_h + (size_t)n * kF + c4) = tot;
}

// ---------------- final GEMM: out = g_h(N,128) @ Wl(128,64) + bl -------------
__global__ __launch_bounds__(256) void gemm_out_kernel(
    const float* __restrict__ A, const float* __restrict__ B,
    const float* __restrict__ bl, float* __restrict__ C) {
    int m0 = blockIdx.x * 128;
    __shared__ float As[8][128];
    __shared__ float Bs[8][64];
    int t = threadIdx.x;
    int ty = t >> 4;
    int tx = t & 15;
    float acc[8][4];
#pragma unroll
    for (int i = 0; i < 8; i++)
#pragma unroll
        for (int j = 0; j < 4; j++) acc[i][j] = 0.f;

    for (int k0 = 0; k0 < kF; k0 += 8) {
        {
            int row = t >> 1;
            int seg = (t & 1) * 4;
            int gr = m0 + row;
            float4 a4 = make_float4(0.f, 0.f, 0.f, 0.f);
            if (gr < kN) a4 = *(const float4*)(A + (size_t)gr * kF + k0 + seg);
            As[seg + 0][row] = a4.x; As[seg + 1][row] = a4.y;
            As[seg + 2][row] = a4.z; As[seg + 3][row] = a4.w;
            if (t < 128) {
                int brow = t >> 4;
                int bcol = (t & 15) * 4;
                *(float4*)(&Bs[brow][bcol]) = *(const float4*)(B + (size_t)(k0 + brow) * kOUT + bcol);
            }
        }
        __syncthreads();
#pragma unroll
        for (int kk = 0; kk < 8; kk++) {
            float ra[8], rb[4];
#pragma unroll
            for (int i = 0; i < 8; i++) ra[i] = As[kk][ty * 8 + i];
#pragma unroll
            for (int j = 0; j < 4; j++) rb[j] = Bs[kk][tx * 4 + j];
#pragma unroll
            for (int i = 0; i < 8; i++)
#pragma unroll
                for (int j = 0; j < 4; j++) acc[i][j] += ra[i] * rb[j];
        }
        __syncthreads();
    }
#pragma unroll
    for (int i = 0; i < 8; i++) {
        int gr = m0 + ty * 8 + i;
        if (gr < kN) {
            float4 v = make_float4(acc[i][0] + bl[tx * 4 + 0], acc[i][1] + bl[tx * 4 + 1],
                                   acc[i][2] + bl[tx * 4 + 2], acc[i][3] + bl[tx * 4 + 3]);
            *(float4*)(C + (size_t)gr * kOUT + tx * 4) = v;
        }
    }
}

extern "C" void kernel_launch(void* const* d_in, const int* in_sizes, int n_in,
                              void* d_out, int out_size) {
    const float* x     = (const float*)d_in[0];
    const int*   edges = (const int*)d_in[1];   // JAX x64 disabled -> int32
    const float* W1    = (const float*)d_in[2];
    const float* al1   = (const float*)d_in[3];
    const float* ar1   = (const float*)d_in[4];
    const float* b1    = (const float*)d_in[5];
    const float* W2    = (const float*)d_in[6];
    const float* al2   = (const float*)d_in[7];
    const float* ar2   = (const float*)d_in[8];
    const float* b2    = (const float*)d_in[9];
    const float* Wl    = (const float*)d_in[10];
    const float* bl    = (const float*)d_in[11];
    float*       out   = (float*)d_out;

    float *hbuf = nullptr, *xtf = nullptr, *wtf = nullptr;
    cudaGetSymbolAddress((void**)&hbuf, g_h);
    cudaGetSymbolAddress((void**)&xtf, g_xtf);
    cudaGetSymbolAddress((void**)&wtf, g_wtf);

    const int TB = 256;
    const int GEMM_SMEM = (2 * 128 * AS_LD + 2 * 32 * BS_LD) * 4;  // 70656 B
    static int attr_set = 0;
    if (!attr_set) {
        cudaFuncSetAttribute(gemm_feat_tc, cudaFuncAttributeMaxDynamicSharedMemorySize, GEMM_SMEM);
        attr_set = 1;
    }
    dim3 gemm_grid((kN + 127) / 128, 1, kR);

    // 0,1: pre-round W and x to tf32
    cvt_w_kernel<<<(2 * kR * kF * kF + TB - 1) / TB, TB>>>(W1, W2);
    cvt_x_kernel<<<(kN * kF / 4 + TB - 1) / TB, TB>>>(x);
    // 2: zero hist
    zero_hist_kernel<<<(kR * kN + TB - 1) / TB, TB>>>();
    // 3: layer-1 GEMM (profiled slot; control — unchanged, expect ~98us)
    gemm_feat_tc<<<gemm_grid, TB, GEMM_SMEM>>>(xtf, wtf, al1, ar1);
    // 4-6: CSR build
    hist_kernel<<<(kR * kE + TB - 1) / TB, TB>>>(edges);
    scan_kernel<<<kR, 1024>>>();
    scatter_kernel<<<(kR * kE + TB - 1) / TB, TB>>>(edges);
    // 7: layer-1 aggregate
    aggregate_kernel<<<(kN * 32 + TB - 1) / TB, TB>>>(b1, 1);
    // 8-9: layer 2
    gemm_feat_tc<<<gemm_grid, TB, GEMM_SMEM>>>(hbuf, wtf + kR * kF * kF, al2, ar2);
    aggregate_kernel<<<(kN * 32 + TB - 1) / TB, TB>>>(b2, 0);
    // 10: final linear
    gemm_out_kernel<<<(kN + 127) / 128, TB>>>(hbuf, Wl, bl, out);
}